// round 4
// baseline (speedup 1.0000x reference)
#include <cuda_runtime.h>
#include <math.h>
#include <stdint.h>

// ---------------- problem constants ----------------
#define BB     8
#define HHT    32
#define WWD    32
#define LL     6
#define RR     384
#define NHEAD  6
#define DHD    64
#define NED    2304          // L*R
#define HIDD   9216          // 4*NE
#define MMD    1365          // unique tree nodes
#define BMROWS (BB*MMD)      // 10920
#define BHWD   8192          // B*H*W
#define NROWS  49152         // B*H*W*L

// ---------------- scratch (static device memory; no allocs) ----------------
__device__ float g_uniq[(size_t)BB*MMD*RR];
__device__ float g_q[(size_t)BB*MMD*RR];
__device__ float g_k[(size_t)BB*MMD*RR];
__device__ float g_v[(size_t)BB*MMD*RR];
__device__ float g_oattn[(size_t)BB*MMD*RR];
__device__ float g_attnout[(size_t)BB*MMD*RR];
__device__ float g_xres[(size_t)NROWS*RR];
__device__ float g_xln2[(size_t)NROWS*RR];
__device__ float g_h1[(size_t)BHWD*HIDD];

__constant__ int c_offs[LL] = {0, 1024, 1280, 1344, 1360, 1364};

// ---------------- LN1 + segment-mean scatter ----------------
__global__ void __launch_bounds__(128) k_ln1_scatter(
    const float* __restrict__ x, const float* __restrict__ gw, const float* __restrict__ gb)
{
    int row = blockIdx.x;
    int l = row % LL; int t = row / LL;
    int w = t % WWD;  t /= WWD;
    int h = t % HHT;  int b = t / HHT;

    const float* xp = x + (size_t)row * RR;
    int tid = threadIdx.x;
    float v[3]; float s1 = 0.f, s2 = 0.f;
#pragma unroll
    for (int i = 0; i < 3; i++) {
        float vv = xp[tid + i*128];
        v[i] = vv; s1 += vv; s2 += vv*vv;
    }
#pragma unroll
    for (int o = 16; o > 0; o >>= 1) {
        s1 += __shfl_xor_sync(0xffffffffu, s1, o);
        s2 += __shfl_xor_sync(0xffffffffu, s2, o);
    }
    __shared__ float sh[8];
    int wid = tid >> 5, ln = tid & 31;
    if (ln == 0) { sh[wid] = s1; sh[4+wid] = s2; }
    __syncthreads();
    s1 = sh[0]+sh[1]+sh[2]+sh[3];
    s2 = sh[4]+sh[5]+sh[6]+sh[7];
    float mu   = s1 * (1.0f/RR);
    float var  = s2 * (1.0f/RR) - mu*mu;
    float rstd = rsqrtf(var + 1e-5f);

    int id = c_offs[l] + (h >> l) * (WWD >> l) + (w >> l);
    float invc = 1.0f / (float)(1 << (2*l));
    float* up = &g_uniq[((size_t)b*MMD + id)*RR];
#pragma unroll
    for (int i = 0; i < 3; i++) {
        int c = tid + i*128;
        float y = (v[i] - mu) * rstd * gw[c] + gb[c];
        atomicAdd(&up[c], y * invc);
    }
}

// ---------------- residual + LN2 ----------------
__global__ void __launch_bounds__(128) k_resid_ln2(
    const float* __restrict__ x, const float* __restrict__ gw, const float* __restrict__ gb)
{
    int row = blockIdx.x;
    int l = row % LL; int t = row / LL;
    int w = t % WWD;  t /= WWD;
    int h = t % HHT;  int b = t / HHT;
    int id = c_offs[l] + (h >> l) * (WWD >> l) + (w >> l);

    const float* xp = x + (size_t)row*RR;
    const float* ap = &g_attnout[((size_t)b*MMD + id)*RR];
    float* rp = &g_xres[(size_t)row*RR];
    float* op = &g_xln2[(size_t)row*RR];

    int tid = threadIdx.x;
    float v[3]; float s1 = 0.f, s2 = 0.f;
#pragma unroll
    for (int i = 0; i < 3; i++) {
        int c = tid + i*128;
        float vv = xp[c] + ap[c];
        rp[c] = vv;
        v[i] = vv; s1 += vv; s2 += vv*vv;
    }
#pragma unroll
    for (int o = 16; o > 0; o >>= 1) {
        s1 += __shfl_xor_sync(0xffffffffu, s1, o);
        s2 += __shfl_xor_sync(0xffffffffu, s2, o);
    }
    __shared__ float sh[8];
    int wid = tid >> 5, ln = tid & 31;
    if (ln == 0) { sh[wid] = s1; sh[4+wid] = s2; }
    __syncthreads();
    s1 = sh[0]+sh[1]+sh[2]+sh[3];
    s2 = sh[4]+sh[5]+sh[6]+sh[7];
    float mu   = s1 * (1.0f/RR);
    float var  = s2 * (1.0f/RR) - mu*mu;
    float rstd = rsqrtf(var + 1e-5f);
#pragma unroll
    for (int i = 0; i < 3; i++) {
        int c = tid + i*128;
        op[c] = (v[i] - mu) * rstd * gw[c] + gb[c];
    }
}

// ---------------- tiled SGEMM: C = act(A@W + bias) (+resid) ----------------
// A: (Ma,K) row-major, W: (K,N) row-major, 128x128 tile, 8x8 micro, 256 thr.
template<bool DOGELU, bool DORESID>
__global__ void __launch_bounds__(256) k_sgemm(
    const float* __restrict__ A, const float* __restrict__ Wm,
    const float* __restrict__ bias, const float* __restrict__ Rm,
    float* __restrict__ C, int Ma, int N, int K)
{
    __shared__ float As[16][132];
    __shared__ float Ws[16][128];
    int tid  = threadIdx.x;
    int row0 = blockIdx.y * 128, col0 = blockIdx.x * 128;
    int trow = (tid >> 4) << 3, tcol = (tid & 15) << 3;

    float acc[8][8];
#pragma unroll
    for (int i = 0; i < 8; i++)
#pragma unroll
        for (int j = 0; j < 8; j++) acc[i][j] = 0.f;

    for (int k0 = 0; k0 < K; k0 += 16) {
#pragma unroll
        for (int i = 0; i < 2; i++) {
            int t = (tid << 1) + i;           // 0..511
            int r = t >> 2, kc = (t & 3) << 2;
            float4 av = make_float4(0.f, 0.f, 0.f, 0.f);
            int gr = row0 + r;
            if (gr < Ma) av = *reinterpret_cast<const float4*>(&A[(size_t)gr*K + k0 + kc]);
            As[kc+0][r] = av.x; As[kc+1][r] = av.y; As[kc+2][r] = av.z; As[kc+3][r] = av.w;
        }
#pragma unroll
        for (int i = 0; i < 2; i++) {
            int t = (tid << 1) + i;
            int kr = t >> 5, c = (t & 31) << 2;
            *reinterpret_cast<float4*>(&Ws[kr][c]) =
                *reinterpret_cast<const float4*>(&Wm[(size_t)(k0 + kr)*N + col0 + c]);
        }
        __syncthreads();
#pragma unroll
        for (int kk = 0; kk < 16; kk++) {
            float4 a0 = *reinterpret_cast<float4*>(&As[kk][trow]);
            float4 a1 = *reinterpret_cast<float4*>(&As[kk][trow+4]);
            float4 b0 = *reinterpret_cast<float4*>(&Ws[kk][tcol]);
            float4 b1 = *reinterpret_cast<float4*>(&Ws[kk][tcol+4]);
            float av[8] = {a0.x,a0.y,a0.z,a0.w,a1.x,a1.y,a1.z,a1.w};
            float bv[8] = {b0.x,b0.y,b0.z,b0.w,b1.x,b1.y,b1.z,b1.w};
#pragma unroll
            for (int i = 0; i < 8; i++)
#pragma unroll
                for (int j = 0; j < 8; j++) acc[i][j] += av[i]*bv[j];
        }
        __syncthreads();
    }

#pragma unroll
    for (int i = 0; i < 8; i++) {
        int gr = row0 + trow + i;
        if (gr < Ma) {
#pragma unroll
            for (int j = 0; j < 8; j++) {
                int gc = col0 + tcol + j;
                float vv = acc[i][j] + bias[gc];
                if (DOGELU) {
                    float x3 = vv*vv*vv;
                    vv = 0.5f * vv * (1.f + tanhf(0.7978845608028654f * (vv + 0.044715f*x3)));
                }
                if (DORESID) vv += Rm[(size_t)gr*N + gc];
                C[(size_t)gr*N + gc] = vv;
            }
        }
    }
}

// ---------------- flash attention over M tree nodes ----------------
// grid: (ceil(M/64), NHEAD, B); 256 threads, 4x4 micro over 64x64 tiles.
__global__ void __launch_bounds__(256) k_attn(
    const float* __restrict__ gq, const float* __restrict__ gk,
    const float* __restrict__ gv, float* __restrict__ go)
{
    extern __shared__ float sm[];
    float* Qs = sm;                   // [64][64]
    float* Ks = sm + 64*64;           // [64][65]
    float* Vs = Ks + 64*65;           // [64][65]
    float* Ps = Vs + 64*65;           // [64][65]

    int rt = blockIdx.x, hh = blockIdx.y, b = blockIdx.z;
    int tid = threadIdx.x;
    int ty = tid >> 4, tx = tid & 15;

    for (int i = tid; i < 64*DHD; i += 256) {
        int r = i >> 6, d = i & 63;
        int m = rt*64 + r;
        Qs[r*64 + d] = (m < MMD) ? gq[((size_t)b*MMD + m)*RR + hh*DHD + d] : 0.f;
    }
    float acc[4][4];
    float mrow[4], lrow[4];
#pragma unroll
    for (int i = 0; i < 4; i++) {
        mrow[i] = -INFINITY; lrow[i] = 0.f;
#pragma unroll
        for (int j = 0; j < 4; j++) acc[i][j] = 0.f;
    }
    __syncthreads();

    int ntiles = (MMD + 63) / 64;
    for (int kt = 0; kt < ntiles; kt++) {
        for (int i = tid; i < 64*DHD; i += 256) {
            int r = i >> 6, d = i & 63;
            int n = kt*64 + r;
            bool ok = (n < MMD);
            size_t base = ((size_t)b*MMD + n)*RR + hh*DHD + d;
            Ks[r*65 + d] = ok ? gk[base] : 0.f;
            Vs[r*65 + d] = ok ? gv[base] : 0.f;
        }
        __syncthreads();

        float s[4][4];
#pragma unroll
        for (int i = 0; i < 4; i++)
#pragma unroll
            for (int j = 0; j < 4; j++) s[i][j] = 0.f;
        for (int d = 0; d < DHD; d++) {
            float av[4], bv[4];
#pragma unroll
            for (int i = 0; i < 4; i++) av[i] = Qs[(ty*4+i)*64 + d];
#pragma unroll
            for (int j = 0; j < 4; j++) bv[j] = Ks[(tx*4+j)*65 + d];
#pragma unroll
            for (int i = 0; i < 4; i++)
#pragma unroll
                for (int j = 0; j < 4; j++) s[i][j] += av[i]*bv[j];
        }
        const float sc = 0.125f;   // 1/sqrt(64)
#pragma unroll
        for (int i = 0; i < 4; i++)
#pragma unroll
            for (int j = 0; j < 4; j++) {
                int n = kt*64 + tx*4 + j;
                s[i][j] = (n < MMD) ? s[i][j]*sc : -INFINITY;
            }

#pragma unroll
        for (int i = 0; i < 4; i++) {
            float mv = fmaxf(fmaxf(s[i][0], s[i][1]), fmaxf(s[i][2], s[i][3]));
#pragma unroll
            for (int o = 8; o > 0; o >>= 1) mv = fmaxf(mv, __shfl_xor_sync(0xffffffffu, mv, o));
            float mn   = fmaxf(mrow[i], mv);
            float corr = __expf(mrow[i] - mn);
            float ps = 0.f;
#pragma unroll
            for (int j = 0; j < 4; j++) {
                float p = __expf(s[i][j] - mn);
                s[i][j] = p; ps += p;
            }
#pragma unroll
            for (int o = 8; o > 0; o >>= 1) ps += __shfl_xor_sync(0xffffffffu, ps, o);
            lrow[i] = lrow[i]*corr + ps;
            mrow[i] = mn;
#pragma unroll
            for (int j = 0; j < 4; j++) {
                acc[i][j] *= corr;
                Ps[(ty*4+i)*65 + tx*4 + j] = s[i][j];
            }
        }
        __syncthreads();

        for (int c = 0; c < 64; c++) {
            float av[4], bv[4];
#pragma unroll
            for (int i = 0; i < 4; i++) av[i] = Ps[(ty*4+i)*65 + c];
#pragma unroll
            for (int j = 0; j < 4; j++) bv[j] = Vs[c*65 + tx*4 + j];
#pragma unroll
            for (int i = 0; i < 4; i++)
#pragma unroll
                for (int j = 0; j < 4; j++) acc[i][j] += av[i]*bv[j];
        }
        __syncthreads();
    }

#pragma unroll
    for (int i = 0; i < 4; i++) {
        int m = rt*64 + ty*4 + i;
        if (m < MMD) {
            float inv_l = 1.0f / lrow[i];
#pragma unroll
            for (int j = 0; j < 4; j++)
                go[((size_t)b*MMD + m)*RR + hh*DHD + tx*4 + j] = acc[i][j]*inv_l;
        }
    }
}

// ---------------- launcher ----------------
extern "C" void kernel_launch(void* const* d_in, const int* in_sizes, int n_in,
                              void* d_out, int out_size)
{
    (void)in_sizes; (void)n_in; (void)out_size;
    const float* x    = (const float*)d_in[0];
    const float* ln1w = (const float*)d_in[1];
    const float* ln1b = (const float*)d_in[2];
    const float* ln2w = (const float*)d_in[3];
    const float* ln2b = (const float*)d_in[4];
    const float* wq   = (const float*)d_in[5];
    const float* bq   = (const float*)d_in[6];
    const float* wk   = (const float*)d_in[7];
    const float* bk   = (const float*)d_in[8];
    const float* wv   = (const float*)d_in[9];
    const float* bv   = (const float*)d_in[10];
    const float* wo   = (const float*)d_in[11];
    const float* bo   = (const float*)d_in[12];
    const float* w1   = (const float*)d_in[13];
    const float* b1   = (const float*)d_in[14];
    const float* w2   = (const float*)d_in[15];
    const float* b2   = (const float*)d_in[16];

    float *p_uniq, *p_q, *p_k, *p_v, *p_o, *p_ao, *p_xres, *p_xln2, *p_h1;
    cudaGetSymbolAddress((void**)&p_uniq, g_uniq);
    cudaGetSymbolAddress((void**)&p_q,    g_q);
    cudaGetSymbolAddress((void**)&p_k,    g_k);
    cudaGetSymbolAddress((void**)&p_v,    g_v);
    cudaGetSymbolAddress((void**)&p_o,    g_oattn);
    cudaGetSymbolAddress((void**)&p_ao,   g_attnout);
    cudaGetSymbolAddress((void**)&p_xres, g_xres);
    cudaGetSymbolAddress((void**)&p_xln2, g_xln2);
    cudaGetSymbolAddress((void**)&p_h1,   g_h1);

    cudaMemsetAsync(p_uniq, 0, sizeof(float)*(size_t)BB*MMD*RR, 0);

    k_ln1_scatter<<<NROWS, 128>>>(x, ln1w, ln1b);

    dim3 gqkv(RR/128, (BMROWS + 127)/128);
    k_sgemm<false,false><<<gqkv, 256>>>(p_uniq, wq, bq, nullptr, p_q, BMROWS, RR, RR);
    k_sgemm<false,false><<<gqkv, 256>>>(p_uniq, wk, bk, nullptr, p_k, BMROWS, RR, RR);
    k_sgemm<false,false><<<gqkv, 256>>>(p_uniq, wv, bv, nullptr, p_v, BMROWS, RR, RR);

    size_t attn_smem = (size_t)(64*64 + 3*64*65) * sizeof(float);   // ~66.3 KB
    cudaFuncSetAttribute(k_attn, cudaFuncAttributeMaxDynamicSharedMemorySize, (int)attn_smem);
    k_attn<<<dim3((MMD+63)/64, NHEAD, BB), 256, attn_smem>>>(p_q, p_k, p_v, p_o);

    k_sgemm<false,false><<<gqkv, 256>>>(p_o, wo, bo, nullptr, p_ao, BMROWS, RR, RR);

    k_resid_ln2<<<NROWS, 128>>>(x, ln2w, ln2b);

    dim3 g1(HIDD/128, BHWD/128);
    k_sgemm<true,false><<<g1, 256>>>(p_xln2, w1, b1, nullptr, p_h1, BHWD, HIDD, NED);

    dim3 g2(NED/128, BHWD/128);
    k_sgemm<false,true><<<g2, 256>>>(p_h1, w2, b2, p_xres, (float*)d_out, BHWD, NED, HIDD);
}

// round 6
// speedup vs baseline: 2.8078x; 2.8078x over previous
#include <cuda_runtime.h>
#include <cuda_bf16.h>
#include <math.h>
#include <stdint.h>

// ---------------- problem constants ----------------
#define BB     8
#define HHT    32
#define WWD    32
#define LL     6
#define RR     384
#define NHEAD  6
#define DHD    64
#define NED    2304          // L*R
#define HIDD   9216          // 4*NE
#define MMD    1365          // unique tree nodes
#define BMROWS (BB*MMD)      // 10920
#define BHWD   8192          // B*H*W
#define NROWS  49152         // B*H*W*L

// ---------------- scratch (static device memory; no allocs) ----------------
__device__ float g_uniq[(size_t)BB*MMD*RR];
__device__ float g_q[(size_t)BB*MMD*RR];
__device__ float g_k[(size_t)BB*MMD*RR];
__device__ float g_v[(size_t)BB*MMD*RR];
__device__ float g_oattn[(size_t)BB*MMD*RR];
__device__ float g_attnout[(size_t)BB*MMD*RR];
__device__ float g_xres[(size_t)NROWS*RR];
__device__ float g_xln2[(size_t)NROWS*RR];
__device__ float g_h1[(size_t)BHWD*HIDD];

__constant__ int c_offs[LL] = {0, 1024, 1280, 1344, 1360, 1364};

__device__ __forceinline__ float gelu_t(float v) {
    float x3 = v*v*v;
    return 0.5f * v * (1.f + tanhf(0.7978845608028654f * (v + 0.044715f*x3)));
}
__device__ __forceinline__ uint32_t smem_u32(const void* p) {
    uint32_t a;
    asm("{ .reg .u64 t; cvta.to.shared.u64 t, %1; cvt.u32.u64 %0, t; }" : "=r"(a) : "l"(p));
    return a;
}
__device__ __forceinline__ uint32_t f2tf32(float f) {
    uint32_t r;
    asm("cvt.rna.tf32.f32 %0, %1;" : "=r"(r) : "f"(f));
    return r;
}
__device__ __forceinline__ void cp16(uint32_t sa, const void* gp, bool pred) {
    asm volatile("cp.async.ca.shared.global [%0], [%1], 16, %2;"
                 :: "r"(sa), "l"(gp), "r"(pred ? 16u : 0u));
}
__device__ __forceinline__ void cp16u(uint32_t sa, const void* gp) {
    asm volatile("cp.async.ca.shared.global [%0], [%1], 16;" :: "r"(sa), "l"(gp));
}
#define CP_COMMIT() asm volatile("cp.async.commit_group;" ::: "memory")
#define CP_WAIT1()  asm volatile("cp.async.wait_group 1;" ::: "memory")
#define CP_WAIT0()  asm volatile("cp.async.wait_group 0;" ::: "memory")

__device__ __forceinline__ void mma_tf32(float& c0, float& c1, float& c2, float& c3,
                                         uint32_t a0, uint32_t a1, uint32_t a2, uint32_t a3,
                                         uint32_t b0, uint32_t b1) {
    asm volatile(
        "mma.sync.aligned.m16n8k8.row.col.f32.tf32.tf32.f32 "
        "{%0,%1,%2,%3}, {%4,%5,%6,%7}, {%8,%9}, {%0,%1,%2,%3};"
        : "+f"(c0), "+f"(c1), "+f"(c2), "+f"(c3)
        : "r"(a0), "r"(a1), "r"(a2), "r"(a3), "r"(b0), "r"(b1));
}

// =====================================================================
// tf32 tensor-core GEMM: C(Ma,N) = act(A(Ma,K) @ W(K,N) + bias) [+resid]
// CTA tile 128x128, BK=32, 256 threads, warps 2(m) x 4(n), warp 64x32.
// N % 128 == 0, K % 32 == 0; Ma arbitrary (guards on A rows / C rows).
// =====================================================================
#define ASTRIDE 36
#define BSTRIDE 132
#define A_ELEMS (128*ASTRIDE)      // 4608 floats / stage
#define B_ELEMS (32*BSTRIDE)       // 4224 floats / stage
#define SMEM_GEMM ((2*A_ELEMS + 2*B_ELEMS)*4)   // 70656 bytes

template<bool DOGELU, bool DORESID>
__global__ void __launch_bounds__(256, 1) k_tf32gemm(
    const float* __restrict__ A, const float* __restrict__ Wm,
    const float* __restrict__ bias, const float* __restrict__ Rm,
    float* __restrict__ C, int Ma, int N, int K)
{
    extern __shared__ __align__(16) float smemf[];
    float* Abase = smemf;                    // 2 stages of A
    float* Bbase = smemf + 2*A_ELEMS;        // 2 stages of B
    const uint32_t sA = smem_u32(Abase);
    const uint32_t sB = smem_u32(Bbase);

    const int tid = threadIdx.x;
    const int wid = tid >> 5, lane = tid & 31;
    const int wm = wid >> 2, wn = wid & 3;   // 2 x 4 warp grid
    const int r = lane >> 2, c4 = lane & 3;

    const int m0 = blockIdx.y * 128, n0 = blockIdx.x * 128;
    const int NC = K >> 5;

    float acc[4][4][4];
#pragma unroll
    for (int i = 0; i < 4; i++)
#pragma unroll
        for (int j = 0; j < 4; j++)
#pragma unroll
            for (int q = 0; q < 4; q++) acc[i][j][q] = 0.f;

    // ---- async fill helper (stage s, chunk kc) ----
    auto fill = [&](int s, int kc) {
        const int k0 = kc << 5;
#pragma unroll
        for (int p = 0; p < 4; p++) {
            int i = tid + p*256;
            int row = i >> 3, cg = (i & 7) << 2;
            bool ok = (m0 + row) < Ma;
            cp16(sA + (uint32_t)(s*A_ELEMS + row*ASTRIDE + cg)*4,
                 A + (size_t)(m0 + row)*K + k0 + cg, ok);
        }
#pragma unroll
        for (int p = 0; p < 4; p++) {
            int i = tid + p*256;
            int kr = i >> 5, cg = (i & 31) << 2;
            cp16u(sB + (uint32_t)(s*B_ELEMS + kr*BSTRIDE + cg)*4,
                  Wm + (size_t)(k0 + kr)*N + n0 + cg);
        }
    };

    fill(0, 0); CP_COMMIT();
    if (NC > 1) { fill(1, 1); CP_COMMIT(); }

    for (int kc = 0; kc < NC; kc++) {
        if (kc + 1 < NC) CP_WAIT1(); else CP_WAIT0();
        __syncthreads();
        const int s = kc & 1;
        const float* As = Abase + s*A_ELEMS;
        const float* Bs = Bbase + s*B_ELEMS;

#pragma unroll
        for (int ks = 0; ks < 4; ks++) {
            uint32_t a[4][4], b[4][2];
#pragma unroll
            for (int mf = 0; mf < 4; mf++) {
                int rb = wm*64 + mf*16;
                a[mf][0] = f2tf32(As[(rb + r    )*ASTRIDE + ks*8 + c4    ]);
                a[mf][1] = f2tf32(As[(rb + r + 8)*ASTRIDE + ks*8 + c4    ]);
                a[mf][2] = f2tf32(As[(rb + r    )*ASTRIDE + ks*8 + c4 + 4]);
                a[mf][3] = f2tf32(As[(rb + r + 8)*ASTRIDE + ks*8 + c4 + 4]);
            }
#pragma unroll
            for (int nf = 0; nf < 4; nf++) {
                int cb = wn*32 + nf*8 + r;
                b[nf][0] = f2tf32(Bs[(ks*8 + c4    )*BSTRIDE + cb]);
                b[nf][1] = f2tf32(Bs[(ks*8 + c4 + 4)*BSTRIDE + cb]);
            }
#pragma unroll
            for (int mf = 0; mf < 4; mf++)
#pragma unroll
                for (int nf = 0; nf < 4; nf++)
                    mma_tf32(acc[mf][nf][0], acc[mf][nf][1], acc[mf][nf][2], acc[mf][nf][3],
                             a[mf][0], a[mf][1], a[mf][2], a[mf][3],
                             b[nf][0], b[nf][1]);
        }
        __syncthreads();
        int kn = kc + 2;
        if (kn < NC) { fill(s, kn); CP_COMMIT(); }
    }

    // ---- epilogue ----
#pragma unroll
    for (int mf = 0; mf < 4; mf++) {
        int grow0 = m0 + wm*64 + mf*16 + r;
#pragma unroll
        for (int nf = 0; nf < 4; nf++) {
            int gcol = n0 + wn*32 + nf*8 + 2*c4;
            float b0 = bias[gcol], b1 = bias[gcol + 1];
#pragma unroll
            for (int hh = 0; hh < 2; hh++) {
                int grow = grow0 + hh*8;
                if (grow < Ma) {
                    float v0 = acc[mf][nf][hh*2 + 0] + b0;
                    float v1 = acc[mf][nf][hh*2 + 1] + b1;
                    if (DOGELU) { v0 = gelu_t(v0); v1 = gelu_t(v1); }
                    if (DORESID) {
                        v0 += Rm[(size_t)grow*N + gcol];
                        v1 += Rm[(size_t)grow*N + gcol + 1];
                    }
                    *reinterpret_cast<float2*>(&C[(size_t)grow*N + gcol]) = make_float2(v0, v1);
                }
            }
        }
    }
}

// ---------------- LN1 + segment-mean scatter ----------------
__global__ void __launch_bounds__(128) k_ln1_scatter(
    const float* __restrict__ x, const float* __restrict__ gw, const float* __restrict__ gb)
{
    int row = blockIdx.x;
    int l = row % LL; int t = row / LL;
    int w = t % WWD;  t /= WWD;
    int h = t % HHT;  int b = t / HHT;

    const float* xp = x + (size_t)row * RR;
    int tid = threadIdx.x;
    float v[3]; float s1 = 0.f, s2 = 0.f;
#pragma unroll
    for (int i = 0; i < 3; i++) {
        float vv = xp[tid + i*128];
        v[i] = vv; s1 += vv; s2 += vv*vv;
    }
#pragma unroll
    for (int o = 16; o > 0; o >>= 1) {
        s1 += __shfl_xor_sync(0xffffffffu, s1, o);
        s2 += __shfl_xor_sync(0xffffffffu, s2, o);
    }
    __shared__ float sh[8];
    int wid = tid >> 5, ln = tid & 31;
    if (ln == 0) { sh[wid] = s1; sh[4+wid] = s2; }
    __syncthreads();
    s1 = sh[0]+sh[1]+sh[2]+sh[3];
    s2 = sh[4]+sh[5]+sh[6]+sh[7];
    float mu   = s1 * (1.0f/RR);
    float var  = s2 * (1.0f/RR) - mu*mu;
    float rstd = rsqrtf(var + 1e-5f);

    int id = c_offs[l] + (h >> l) * (WWD >> l) + (w >> l);
    float invc = 1.0f / (float)(1 << (2*l));
    float* up = &g_uniq[((size_t)b*MMD + id)*RR];
#pragma unroll
    for (int i = 0; i < 3; i++) {
        int c = tid + i*128;
        float y = (v[i] - mu) * rstd * gw[c] + gb[c];
        atomicAdd(&up[c], y * invc);
    }
}

// ---------------- residual + LN2 ----------------
__global__ void __launch_bounds__(128) k_resid_ln2(
    const float* __restrict__ x, const float* __restrict__ gw, const float* __restrict__ gb)
{
    int row = blockIdx.x;
    int l = row % LL; int t = row / LL;
    int w = t % WWD;  t /= WWD;
    int h = t % HHT;  int b = t / HHT;
    int id = c_offs[l] + (h >> l) * (WWD >> l) + (w >> l);

    const float* xp = x + (size_t)row*RR;
    const float* ap = &g_attnout[((size_t)b*MMD + id)*RR];
    float* rp = &g_xres[(size_t)row*RR];
    float* op = &g_xln2[(size_t)row*RR];

    int tid = threadIdx.x;
    float v[3]; float s1 = 0.f, s2 = 0.f;
#pragma unroll
    for (int i = 0; i < 3; i++) {
        int c = tid + i*128;
        float vv = xp[c] + ap[c];
        rp[c] = vv;
        v[i] = vv; s1 += vv; s2 += vv*vv;
    }
#pragma unroll
    for (int o = 16; o > 0; o >>= 1) {
        s1 += __shfl_xor_sync(0xffffffffu, s1, o);
        s2 += __shfl_xor_sync(0xffffffffu, s2, o);
    }
    __shared__ float sh[8];
    int wid = tid >> 5, ln = tid & 31;
    if (ln == 0) { sh[wid] = s1; sh[4+wid] = s2; }
    __syncthreads();
    s1 = sh[0]+sh[1]+sh[2]+sh[3];
    s2 = sh[4]+sh[5]+sh[6]+sh[7];
    float mu   = s1 * (1.0f/RR);
    float var  = s2 * (1.0f/RR) - mu*mu;
    float rstd = rsqrtf(var + 1e-5f);
#pragma unroll
    for (int i = 0; i < 3; i++) {
        int c = tid + i*128;
        op[c] = (v[i] - mu) * rstd * gw[c] + gb[c];
    }
}

// ---------------- flash attention over M tree nodes ----------------
__global__ void __launch_bounds__(256) k_attn(
    const float* __restrict__ gq, const float* __restrict__ gk,
    const float* __restrict__ gv, float* __restrict__ go)
{
    extern __shared__ float sm[];
    float* Qs = sm;                   // [64][64]
    float* Ks = sm + 64*64;           // [64][65]
    float* Vs = Ks + 64*65;           // [64][65]
    float* Ps = Vs + 64*65;           // [64][65]

    int rt = blockIdx.x, hh = blockIdx.y, b = blockIdx.z;
    int tid = threadIdx.x;
    int ty = tid >> 4, tx = tid & 15;

    for (int i = tid; i < 64*DHD; i += 256) {
        int r = i >> 6, d = i & 63;
        int m = rt*64 + r;
        Qs[r*64 + d] = (m < MMD) ? gq[((size_t)b*MMD + m)*RR + hh*DHD + d] : 0.f;
    }
    float acc[4][4];
    float mrow[4], lrow[4];
#pragma unroll
    for (int i = 0; i < 4; i++) {
        mrow[i] = -INFINITY; lrow[i] = 0.f;
#pragma unroll
        for (int j = 0; j < 4; j++) acc[i][j] = 0.f;
    }
    __syncthreads();

    int ntiles = (MMD + 63) / 64;
    for (int kt = 0; kt < ntiles; kt++) {
        for (int i = tid; i < 64*DHD; i += 256) {
            int r = i >> 6, d = i & 63;
            int n = kt*64 + r;
            bool ok = (n < MMD);
            size_t base = ((size_t)b*MMD + n)*RR + hh*DHD + d;
            Ks[r*65 + d] = ok ? gk[base] : 0.f;
            Vs[r*65 + d] = ok ? gv[base] : 0.f;
        }
        __syncthreads();

        float s[4][4];
#pragma unroll
        for (int i = 0; i < 4; i++)
#pragma unroll
            for (int j = 0; j < 4; j++) s[i][j] = 0.f;
        for (int d = 0; d < DHD; d++) {
            float av[4], bv[4];
#pragma unroll
            for (int i = 0; i < 4; i++) av[i] = Qs[(ty*4+i)*64 + d];
#pragma unroll
            for (int j = 0; j < 4; j++) bv[j] = Ks[(tx*4+j)*65 + d];
#pragma unroll
            for (int i = 0; i < 4; i++)
#pragma unroll
                for (int j = 0; j < 4; j++) s[i][j] += av[i]*bv[j];
        }
        const float sc = 0.125f;   // 1/sqrt(64)
#pragma unroll
        for (int i = 0; i < 4; i++)
#pragma unroll
            for (int j = 0; j < 4; j++) {
                int n = kt*64 + tx*4 + j;
                s[i][j] = (n < MMD) ? s[i][j]*sc : -INFINITY;
            }

#pragma unroll
        for (int i = 0; i < 4; i++) {
            float mv = fmaxf(fmaxf(s[i][0], s[i][1]), fmaxf(s[i][2], s[i][3]));
#pragma unroll
            for (int o = 8; o > 0; o >>= 1) mv = fmaxf(mv, __shfl_xor_sync(0xffffffffu, mv, o));
            float mn   = fmaxf(mrow[i], mv);
            float corr = __expf(mrow[i] - mn);
            float ps = 0.f;
#pragma unroll
            for (int j = 0; j < 4; j++) {
                float p = __expf(s[i][j] - mn);
                s[i][j] = p; ps += p;
            }
#pragma unroll
            for (int o = 8; o > 0; o >>= 1) ps += __shfl_xor_sync(0xffffffffu, ps, o);
            lrow[i] = lrow[i]*corr + ps;
            mrow[i] = mn;
#pragma unroll
            for (int j = 0; j < 4; j++) {
                acc[i][j] *= corr;
                Ps[(ty*4+i)*65 + tx*4 + j] = s[i][j];
            }
        }
        __syncthreads();

        for (int c = 0; c < 64; c++) {
            float av[4], bv[4];
#pragma unroll
            for (int i = 0; i < 4; i++) av[i] = Ps[(ty*4+i)*65 + c];
#pragma unroll
            for (int j = 0; j < 4; j++) bv[j] = Vs[c*65 + tx*4 + j];
#pragma unroll
            for (int i = 0; i < 4; i++)
#pragma unroll
                for (int j = 0; j < 4; j++) acc[i][j] += av[i]*bv[j];
        }
        __syncthreads();
    }

#pragma unroll
    for (int i = 0; i < 4; i++) {
        int m = rt*64 + ty*4 + i;
        if (m < MMD) {
            float inv_l = 1.0f / lrow[i];
#pragma unroll
            for (int j = 0; j < 4; j++)
                go[((size_t)b*MMD + m)*RR + hh*DHD + tx*4 + j] = acc[i][j]*inv_l;
        }
    }
}

// ---------------- launcher ----------------
extern "C" void kernel_launch(void* const* d_in, const int* in_sizes, int n_in,
                              void* d_out, int out_size)
{
    (void)in_sizes; (void)n_in; (void)out_size;
    const float* x    = (const float*)d_in[0];
    const float* ln1w = (const float*)d_in[1];
    const float* ln1b = (const float*)d_in[2];
    const float* ln2w = (const float*)d_in[3];
    const float* ln2b = (const float*)d_in[4];
    const float* wq   = (const float*)d_in[5];
    const float* bq   = (const float*)d_in[6];
    const float* wk   = (const float*)d_in[7];
    const float* bk   = (const float*)d_in[8];
    const float* wv   = (const float*)d_in[9];
    const float* bv   = (const float*)d_in[10];
    const float* wo   = (const float*)d_in[11];
    const float* bo   = (const float*)d_in[12];
    const float* w1   = (const float*)d_in[13];
    const float* b1   = (const float*)d_in[14];
    const float* w2   = (const float*)d_in[15];
    const float* b2   = (const float*)d_in[16];

    float *p_uniq, *p_q, *p_k, *p_v, *p_o, *p_ao, *p_xres, *p_xln2, *p_h1;
    cudaGetSymbolAddress((void**)&p_uniq, g_uniq);
    cudaGetSymbolAddress((void**)&p_q,    g_q);
    cudaGetSymbolAddress((void**)&p_k,    g_k);
    cudaGetSymbolAddress((void**)&p_v,    g_v);
    cudaGetSymbolAddress((void**)&p_o,    g_oattn);
    cudaGetSymbolAddress((void**)&p_ao,   g_attnout);
    cudaGetSymbolAddress((void**)&p_xres, g_xres);
    cudaGetSymbolAddress((void**)&p_xln2, g_xln2);
    cudaGetSymbolAddress((void**)&p_h1,   g_h1);

    cudaMemsetAsync(p_uniq, 0, sizeof(float)*(size_t)BB*MMD*RR, 0);

    k_ln1_scatter<<<NROWS, 128>>>(x, ln1w, ln1b);

    cudaFuncSetAttribute(k_tf32gemm<false,false>,
                         cudaFuncAttributeMaxDynamicSharedMemorySize, SMEM_GEMM);
    cudaFuncSetAttribute(k_tf32gemm<true,false>,
                         cudaFuncAttributeMaxDynamicSharedMemorySize, SMEM_GEMM);
    cudaFuncSetAttribute(k_tf32gemm<false,true>,
                         cudaFuncAttributeMaxDynamicSharedMemorySize, SMEM_GEMM);

    dim3 gqkv(RR/128, (BMROWS + 127)/128);   // (3, 86)
    k_tf32gemm<false,false><<<gqkv, 256, SMEM_GEMM>>>(p_uniq, wq, bq, nullptr, p_q, BMROWS, RR, RR);
    k_tf32gemm<false,false><<<gqkv, 256, SMEM_GEMM>>>(p_uniq, wk, bk, nullptr, p_k, BMROWS, RR, RR);
    k_tf32gemm<false,false><<<gqkv, 256, SMEM_GEMM>>>(p_uniq, wv, bv, nullptr, p_v, BMROWS, RR, RR);

    size_t attn_smem = (size_t)(64*64 + 3*64*65) * sizeof(float);
    cudaFuncSetAttribute(k_attn, cudaFuncAttributeMaxDynamicSharedMemorySize, (int)attn_smem);
    k_attn<<<dim3((MMD+63)/64, NHEAD, BB), 256, attn_smem>>>(p_q, p_k, p_v, p_o);

    k_tf32gemm<false,false><<<gqkv, 256, SMEM_GEMM>>>(p_o, wo, bo, nullptr, p_ao, BMROWS, RR, RR);

    k_resid_ln2<<<NROWS, 128>>>(x, ln2w, ln2b);

    // MLP GEMM1: h1 = gelu(xln2 @ w1 + b1)
    k_tf32gemm<true,false><<<dim3(HIDD/128, BHWD/128), 256, SMEM_GEMM>>>(
        p_xln2, w1, b1, nullptr, p_h1, BHWD, HIDD, NED);

    // MLP GEMM2: out = h1 @ w2 + b2 + xres
    k_tf32gemm<false,true><<<dim3(NED/128, BHWD/128), 256, SMEM_GEMM>>>(
        p_h1, w2, b2, p_xres, (float*)d_out, BHWD, NED, HIDD);
}

// round 7
// speedup vs baseline: 3.1895x; 1.1360x over previous
#include <cuda_runtime.h>
#include <cuda_bf16.h>
#include <math.h>
#include <stdint.h>

// ---------------- problem constants ----------------
#define BB     8
#define HHT    32
#define WWD    32
#define LL     6
#define RR     384
#define NHEAD  6
#define DHD    64
#define NED    2304          // L*R
#define HIDD   9216          // 4*NE
#define MMD    1365          // unique tree nodes
#define BMROWS (BB*MMD)      // 10920
#define BHWD   8192          // B*H*W
#define NROWS  49152         // B*H*W*L

// ---------------- scratch (static device memory; no allocs) ----------------
__device__ float g_uniq[(size_t)BB*MMD*RR];
__device__ float g_q[(size_t)BB*MMD*RR];
__device__ float g_k[(size_t)BB*MMD*RR];
__device__ float g_v[(size_t)BB*MMD*RR];
__device__ float g_oattn[(size_t)BB*MMD*RR];
__device__ float g_attnout[(size_t)BB*MMD*RR];
__device__ float g_xres[(size_t)NROWS*RR];
__device__ float g_xln2[(size_t)NROWS*RR];
__device__ float g_h1[(size_t)BHWD*HIDD];
// tf32-preconverted weights
__device__ float g_wqt[RR*RR];
__device__ float g_wkt[RR*RR];
__device__ float g_wvt[RR*RR];
__device__ float g_wot[RR*RR];
__device__ float g_w1t[(size_t)NED*HIDD];
__device__ float g_w2t[(size_t)HIDD*NED];

__constant__ int c_offs[LL] = {0, 1024, 1280, 1344, 1360, 1364};

__device__ __forceinline__ float gelu_t(float v) {
    float x3 = v*v*v;
    return 0.5f * v * (1.f + tanhf(0.7978845608028654f * (v + 0.044715f*x3)));
}
__device__ __forceinline__ uint32_t smem_u32(const void* p) {
    uint32_t a;
    asm("{ .reg .u64 t; cvta.to.shared.u64 t, %1; cvt.u32.u64 %0, t; }" : "=r"(a) : "l"(p));
    return a;
}
__device__ __forceinline__ float f2tf32f(float f) {
    uint32_t r;
    asm("cvt.rna.tf32.f32 %0, %1;" : "=r"(r) : "f"(f));
    return __uint_as_float(r);
}
__device__ __forceinline__ void cp16(uint32_t sa, const void* gp, bool pred) {
    asm volatile("cp.async.ca.shared.global [%0], [%1], 16, %2;"
                 :: "r"(sa), "l"(gp), "r"(pred ? 16u : 0u));
}
__device__ __forceinline__ void cp16u(uint32_t sa, const void* gp) {
    asm volatile("cp.async.ca.shared.global [%0], [%1], 16;" :: "r"(sa), "l"(gp));
}
#define CP_COMMIT() asm volatile("cp.async.commit_group;" ::: "memory")
#define CP_WAIT1()  asm volatile("cp.async.wait_group 1;" ::: "memory")
#define CP_WAIT0()  asm volatile("cp.async.wait_group 0;" ::: "memory")

__device__ __forceinline__ void mma_tf32(float& c0, float& c1, float& c2, float& c3,
                                         uint32_t a0, uint32_t a1, uint32_t a2, uint32_t a3,
                                         uint32_t b0, uint32_t b1) {
    asm volatile(
        "mma.sync.aligned.m16n8k8.row.col.f32.tf32.tf32.f32 "
        "{%0,%1,%2,%3}, {%4,%5,%6,%7}, {%8,%9}, {%0,%1,%2,%3};"
        : "+f"(c0), "+f"(c1), "+f"(c2), "+f"(c3)
        : "r"(a0), "r"(a1), "r"(a2), "r"(a3), "r"(b0), "r"(b1));
}

// ---------------- tf32 pre-convert (elementwise, float4) ----------------
__global__ void __launch_bounds__(256) k_cvt(const float* __restrict__ in,
                                             float* __restrict__ out, size_t n4)
{
    size_t i = (size_t)blockIdx.x * blockDim.x + threadIdx.x;
    size_t stride = (size_t)gridDim.x * blockDim.x;
    for (; i < n4; i += stride) {
        float4 v = reinterpret_cast<const float4*>(in)[i];
        v.x = f2tf32f(v.x); v.y = f2tf32f(v.y);
        v.z = f2tf32f(v.z); v.w = f2tf32f(v.w);
        reinterpret_cast<float4*>(out)[i] = v;
    }
}

// =====================================================================
// tf32 tensor-core GEMM: C(Ma,N) = act(A(Ma,K) @ W(K,N) + bias) [+resid]
// A and W must be PRE-ROUNDED to tf32 (bit pattern stored as float).
// CTA tile 128x128, BK=32, 256 threads, warps 2(m) x 4(n), warp 64x32.
// N % 128 == 0, K % 32 == 0; Ma arbitrary (guards on A rows / C rows).
// =====================================================================
#define ASTRIDE 36
#define BSTRIDE 136                    // 136 % 32 == 8 -> conflict-free B frags
#define A_ELEMS (128*ASTRIDE)          // 4608 floats / stage
#define B_ELEMS (32*BSTRIDE)           // 4352 floats / stage
#define SMEM_GEMM ((2*A_ELEMS + 2*B_ELEMS)*4)   // 71680 bytes

template<bool DOGELU, bool DORESID, bool OUTTF32>
__global__ void __launch_bounds__(256, 2) k_tf32gemm(
    const float* __restrict__ A, const float* __restrict__ Wm,
    const float* __restrict__ bias, const float* __restrict__ Rm,
    float* __restrict__ C, int Ma, int N, int K)
{
    extern __shared__ __align__(16) float smemf[];
    float* Abase = smemf;                    // 2 stages of A
    float* Bbase = smemf + 2*A_ELEMS;        // 2 stages of B
    const uint32_t sA = smem_u32(Abase);
    const uint32_t sB = smem_u32(Bbase);

    const int tid = threadIdx.x;
    const int wid = tid >> 5, lane = tid & 31;
    const int wm = wid >> 2, wn = wid & 3;   // 2 x 4 warp grid
    const int r = lane >> 2, c4 = lane & 3;

    const int m0 = blockIdx.y * 128, n0 = blockIdx.x * 128;
    const int NC = K >> 5;

    float acc[4][4][4];
#pragma unroll
    for (int i = 0; i < 4; i++)
#pragma unroll
        for (int j = 0; j < 4; j++)
#pragma unroll
            for (int q = 0; q < 4; q++) acc[i][j][q] = 0.f;

    auto fill = [&](int s, int kc) {
        const int k0 = kc << 5;
#pragma unroll
        for (int p = 0; p < 4; p++) {
            int i = tid + p*256;
            int row = i >> 3, cg = (i & 7) << 2;
            bool ok = (m0 + row) < Ma;
            cp16(sA + (uint32_t)(s*A_ELEMS + row*ASTRIDE + cg)*4,
                 A + (size_t)(m0 + row)*K + k0 + cg, ok);
        }
#pragma unroll
        for (int p = 0; p < 4; p++) {
            int i = tid + p*256;
            int kr = i >> 5, cg = (i & 31) << 2;
            cp16u(sB + (uint32_t)(s*B_ELEMS + kr*BSTRIDE + cg)*4,
                  Wm + (size_t)(k0 + kr)*N + n0 + cg);
        }
    };

    fill(0, 0); CP_COMMIT();
    if (NC > 1) { fill(1, 1); CP_COMMIT(); }

    for (int kc = 0; kc < NC; kc++) {
        if (kc + 1 < NC) CP_WAIT1(); else CP_WAIT0();
        __syncthreads();
        const int s = kc & 1;
        const uint32_t* As = reinterpret_cast<const uint32_t*>(Abase + s*A_ELEMS);
        const uint32_t* Bs = reinterpret_cast<const uint32_t*>(Bbase + s*B_ELEMS);

#pragma unroll
        for (int ks = 0; ks < 4; ks++) {
            uint32_t a[4][4], b[4][2];
#pragma unroll
            for (int mf = 0; mf < 4; mf++) {
                int rb = wm*64 + mf*16;
                a[mf][0] = As[(rb + r    )*ASTRIDE + ks*8 + c4    ];
                a[mf][1] = As[(rb + r + 8)*ASTRIDE + ks*8 + c4    ];
                a[mf][2] = As[(rb + r    )*ASTRIDE + ks*8 + c4 + 4];
                a[mf][3] = As[(rb + r + 8)*ASTRIDE + ks*8 + c4 + 4];
            }
#pragma unroll
            for (int nf = 0; nf < 4; nf++) {
                int cb = wn*32 + nf*8 + r;
                b[nf][0] = Bs[(ks*8 + c4    )*BSTRIDE + cb];
                b[nf][1] = Bs[(ks*8 + c4 + 4)*BSTRIDE + cb];
            }
#pragma unroll
            for (int mf = 0; mf < 4; mf++)
#pragma unroll
                for (int nf = 0; nf < 4; nf++)
                    mma_tf32(acc[mf][nf][0], acc[mf][nf][1], acc[mf][nf][2], acc[mf][nf][3],
                             a[mf][0], a[mf][1], a[mf][2], a[mf][3],
                             b[nf][0], b[nf][1]);
        }
        __syncthreads();
        int kn = kc + 2;
        if (kn < NC) { fill(s, kn); CP_COMMIT(); }
    }

    // ---- epilogue ----
#pragma unroll
    for (int mf = 0; mf < 4; mf++) {
        int grow0 = m0 + wm*64 + mf*16 + r;
#pragma unroll
        for (int nf = 0; nf < 4; nf++) {
            int gcol = n0 + wn*32 + nf*8 + 2*c4;
            float b0 = bias[gcol], b1 = bias[gcol + 1];
#pragma unroll
            for (int hh = 0; hh < 2; hh++) {
                int grow = grow0 + hh*8;
                if (grow < Ma) {
                    float v0 = acc[mf][nf][hh*2 + 0] + b0;
                    float v1 = acc[mf][nf][hh*2 + 1] + b1;
                    if (DOGELU) { v0 = gelu_t(v0); v1 = gelu_t(v1); }
                    if (DORESID) {
                        v0 += Rm[(size_t)grow*N + gcol];
                        v1 += Rm[(size_t)grow*N + gcol + 1];
                    }
                    if (OUTTF32) { v0 = f2tf32f(v0); v1 = f2tf32f(v1); }
                    *reinterpret_cast<float2*>(&C[(size_t)grow*N + gcol]) = make_float2(v0, v1);
                }
            }
        }
    }
}

// ---------------- LN1 + segment-mean scatter ----------------
__global__ void __launch_bounds__(128) k_ln1_scatter(
    const float* __restrict__ x, const float* __restrict__ gw, const float* __restrict__ gb)
{
    int row = blockIdx.x;
    int l = row % LL; int t = row / LL;
    int w = t % WWD;  t /= WWD;
    int h = t % HHT;  int b = t / HHT;

    const float* xp = x + (size_t)row * RR;
    int tid = threadIdx.x;
    float v[3]; float s1 = 0.f, s2 = 0.f;
#pragma unroll
    for (int i = 0; i < 3; i++) {
        float vv = xp[tid + i*128];
        v[i] = vv; s1 += vv; s2 += vv*vv;
    }
#pragma unroll
    for (int o = 16; o > 0; o >>= 1) {
        s1 += __shfl_xor_sync(0xffffffffu, s1, o);
        s2 += __shfl_xor_sync(0xffffffffu, s2, o);
    }
    __shared__ float sh[8];
    int wid = tid >> 5, ln = tid & 31;
    if (ln == 0) { sh[wid] = s1; sh[4+wid] = s2; }
    __syncthreads();
    s1 = sh[0]+sh[1]+sh[2]+sh[3];
    s2 = sh[4]+sh[5]+sh[6]+sh[7];
    float mu   = s1 * (1.0f/RR);
    float var  = s2 * (1.0f/RR) - mu*mu;
    float rstd = rsqrtf(var + 1e-5f);

    int id = c_offs[l] + (h >> l) * (WWD >> l) + (w >> l);
    float invc = 1.0f / (float)(1 << (2*l));
    float* up = &g_uniq[((size_t)b*MMD + id)*RR];
#pragma unroll
    for (int i = 0; i < 3; i++) {
        int c = tid + i*128;
        float y = (v[i] - mu) * rstd * gw[c] + gb[c];
        atomicAdd(&up[c], y * invc);
    }
}

// ---------------- residual + LN2 (xln2 stored pre-rounded to tf32) ----------------
__global__ void __launch_bounds__(128) k_resid_ln2(
    const float* __restrict__ x, const float* __restrict__ gw, const float* __restrict__ gb)
{
    int row = blockIdx.x;
    int l = row % LL; int t = row / LL;
    int w = t % WWD;  t /= WWD;
    int h = t % HHT;  int b = t / HHT;
    int id = c_offs[l] + (h >> l) * (WWD >> l) + (w >> l);

    const float* xp = x + (size_t)row*RR;
    const float* ap = &g_attnout[((size_t)b*MMD + id)*RR];
    float* rp = &g_xres[(size_t)row*RR];
    float* op = &g_xln2[(size_t)row*RR];

    int tid = threadIdx.x;
    float v[3]; float s1 = 0.f, s2 = 0.f;
#pragma unroll
    for (int i = 0; i < 3; i++) {
        int c = tid + i*128;
        float vv = xp[c] + ap[c];
        rp[c] = vv;
        v[i] = vv; s1 += vv; s2 += vv*vv;
    }
#pragma unroll
    for (int o = 16; o > 0; o >>= 1) {
        s1 += __shfl_xor_sync(0xffffffffu, s1, o);
        s2 += __shfl_xor_sync(0xffffffffu, s2, o);
    }
    __shared__ float sh[8];
    int wid = tid >> 5, ln = tid & 31;
    if (ln == 0) { sh[wid] = s1; sh[4+wid] = s2; }
    __syncthreads();
    s1 = sh[0]+sh[1]+sh[2]+sh[3];
    s2 = sh[4]+sh[5]+sh[6]+sh[7];
    float mu   = s1 * (1.0f/RR);
    float var  = s2 * (1.0f/RR) - mu*mu;
    float rstd = rsqrtf(var + 1e-5f);
#pragma unroll
    for (int i = 0; i < 3; i++) {
        int c = tid + i*128;
        op[c] = f2tf32f((v[i] - mu) * rstd * gw[c] + gb[c]);
    }
}

// ---------------- flash attention over M tree nodes ----------------
__global__ void __launch_bounds__(256) k_attn(
    const float* __restrict__ gq, const float* __restrict__ gk,
    const float* __restrict__ gv, float* __restrict__ go)
{
    extern __shared__ float sm[];
    float* Qs = sm;                   // [64][64]
    float* Ks = sm + 64*64;           // [64][65]
    float* Vs = Ks + 64*65;           // [64][65]
    float* Ps = Vs + 64*65;           // [64][65]

    int rt = blockIdx.x, hh = blockIdx.y, b = blockIdx.z;
    int tid = threadIdx.x;
    int ty = tid >> 4, tx = tid & 15;

    for (int i = tid; i < 64*DHD; i += 256) {
        int r = i >> 6, d = i & 63;
        int m = rt*64 + r;
        Qs[r*64 + d] = (m < MMD) ? gq[((size_t)b*MMD + m)*RR + hh*DHD + d] : 0.f;
    }
    float acc[4][4];
    float mrow[4], lrow[4];
#pragma unroll
    for (int i = 0; i < 4; i++) {
        mrow[i] = -INFINITY; lrow[i] = 0.f;
#pragma unroll
        for (int j = 0; j < 4; j++) acc[i][j] = 0.f;
    }
    __syncthreads();

    int ntiles = (MMD + 63) / 64;
    for (int kt = 0; kt < ntiles; kt++) {
        for (int i = tid; i < 64*DHD; i += 256) {
            int r = i >> 6, d = i & 63;
            int n = kt*64 + r;
            bool ok = (n < MMD);
            size_t base = ((size_t)b*MMD + n)*RR + hh*DHD + d;
            Ks[r*65 + d] = ok ? gk[base] : 0.f;
            Vs[r*65 + d] = ok ? gv[base] : 0.f;
        }
        __syncthreads();

        float s[4][4];
#pragma unroll
        for (int i = 0; i < 4; i++)
#pragma unroll
            for (int j = 0; j < 4; j++) s[i][j] = 0.f;
        for (int d = 0; d < DHD; d++) {
            float av[4], bv[4];
#pragma unroll
            for (int i = 0; i < 4; i++) av[i] = Qs[(ty*4+i)*64 + d];
#pragma unroll
            for (int j = 0; j < 4; j++) bv[j] = Ks[(tx*4+j)*65 + d];
#pragma unroll
            for (int i = 0; i < 4; i++)
#pragma unroll
                for (int j = 0; j < 4; j++) s[i][j] += av[i]*bv[j];
        }
        const float sc = 0.125f;   // 1/sqrt(64)
#pragma unroll
        for (int i = 0; i < 4; i++)
#pragma unroll
            for (int j = 0; j < 4; j++) {
                int n = kt*64 + tx*4 + j;
                s[i][j] = (n < MMD) ? s[i][j]*sc : -INFINITY;
            }

#pragma unroll
        for (int i = 0; i < 4; i++) {
            float mv = fmaxf(fmaxf(s[i][0], s[i][1]), fmaxf(s[i][2], s[i][3]));
#pragma unroll
            for (int o = 8; o > 0; o >>= 1) mv = fmaxf(mv, __shfl_xor_sync(0xffffffffu, mv, o));
            float mn   = fmaxf(mrow[i], mv);
            float corr = __expf(mrow[i] - mn);
            float ps = 0.f;
#pragma unroll
            for (int j = 0; j < 4; j++) {
                float p = __expf(s[i][j] - mn);
                s[i][j] = p; ps += p;
            }
#pragma unroll
            for (int o = 8; o > 0; o >>= 1) ps += __shfl_xor_sync(0xffffffffu, ps, o);
            lrow[i] = lrow[i]*corr + ps;
            mrow[i] = mn;
#pragma unroll
            for (int j = 0; j < 4; j++) {
                acc[i][j] *= corr;
                Ps[(ty*4+i)*65 + tx*4 + j] = s[i][j];
            }
        }
        __syncthreads();

        for (int c = 0; c < 64; c++) {
            float av[4], bv[4];
#pragma unroll
            for (int i = 0; i < 4; i++) av[i] = Ps[(ty*4+i)*65 + c];
#pragma unroll
            for (int j = 0; j < 4; j++) bv[j] = Vs[c*65 + tx*4 + j];
#pragma unroll
            for (int i = 0; i < 4; i++)
#pragma unroll
                for (int j = 0; j < 4; j++) acc[i][j] += av[i]*bv[j];
        }
        __syncthreads();
    }

#pragma unroll
    for (int i = 0; i < 4; i++) {
        int m = rt*64 + ty*4 + i;
        if (m < MMD) {
            float inv_l = 1.0f / lrow[i];
#pragma unroll
            for (int j = 0; j < 4; j++)
                go[((size_t)b*MMD + m)*RR + hh*DHD + tx*4 + j] = f2tf32f(acc[i][j]*inv_l);
        }
    }
}

// ---------------- launcher ----------------
extern "C" void kernel_launch(void* const* d_in, const int* in_sizes, int n_in,
                              void* d_out, int out_size)
{
    (void)in_sizes; (void)n_in; (void)out_size;
    const float* x    = (const float*)d_in[0];
    const float* ln1w = (const float*)d_in[1];
    const float* ln1b = (const float*)d_in[2];
    const float* ln2w = (const float*)d_in[3];
    const float* ln2b = (const float*)d_in[4];
    const float* wq   = (const float*)d_in[5];
    const float* bq   = (const float*)d_in[6];
    const float* wk   = (const float*)d_in[7];
    const float* bk   = (const float*)d_in[8];
    const float* wv   = (const float*)d_in[9];
    const float* bv   = (const float*)d_in[10];
    const float* wo   = (const float*)d_in[11];
    const float* bo   = (const float*)d_in[12];
    const float* w1   = (const float*)d_in[13];
    const float* b1   = (const float*)d_in[14];
    const float* w2   = (const float*)d_in[15];
    const float* b2   = (const float*)d_in[16];

    float *p_uniq, *p_q, *p_k, *p_v, *p_o, *p_ao, *p_xres, *p_xln2, *p_h1;
    float *p_wqt, *p_wkt, *p_wvt, *p_wot, *p_w1t, *p_w2t;
    cudaGetSymbolAddress((void**)&p_uniq, g_uniq);
    cudaGetSymbolAddress((void**)&p_q,    g_q);
    cudaGetSymbolAddress((void**)&p_k,    g_k);
    cudaGetSymbolAddress((void**)&p_v,    g_v);
    cudaGetSymbolAddress((void**)&p_o,    g_oattn);
    cudaGetSymbolAddress((void**)&p_ao,   g_attnout);
    cudaGetSymbolAddress((void**)&p_xres, g_xres);
    cudaGetSymbolAddress((void**)&p_xln2, g_xln2);
    cudaGetSymbolAddress((void**)&p_h1,   g_h1);
    cudaGetSymbolAddress((void**)&p_wqt,  g_wqt);
    cudaGetSymbolAddress((void**)&p_wkt,  g_wkt);
    cudaGetSymbolAddress((void**)&p_wvt,  g_wvt);
    cudaGetSymbolAddress((void**)&p_wot,  g_wot);
    cudaGetSymbolAddress((void**)&p_w1t,  g_w1t);
    cudaGetSymbolAddress((void**)&p_w2t,  g_w2t);

    cudaMemsetAsync(p_uniq, 0, sizeof(float)*(size_t)BB*MMD*RR, 0);

    // pre-round weights to tf32 (once per launch)
    k_cvt<<<96,  256>>>(wq, p_wqt, (size_t)RR*RR/4);
    k_cvt<<<96,  256>>>(wk, p_wkt, (size_t)RR*RR/4);
    k_cvt<<<96,  256>>>(wv, p_wvt, (size_t)RR*RR/4);
    k_cvt<<<96,  256>>>(wo, p_wot, (size_t)RR*RR/4);
    k_cvt<<<592, 256>>>(w1, p_w1t, (size_t)NED*HIDD/4);
    k_cvt<<<592, 256>>>(w2, p_w2t, (size_t)HIDD*NED/4);

    k_ln1_scatter<<<NROWS, 128>>>(x, ln1w, ln1b);
    // round uniq to tf32 in place
    k_cvt<<<592, 256>>>(p_uniq, p_uniq, (size_t)BB*MMD*RR/4);

    cudaFuncSetAttribute(k_tf32gemm<false,false,false>,
                         cudaFuncAttributeMaxDynamicSharedMemorySize, SMEM_GEMM);
    cudaFuncSetAttribute(k_tf32gemm<true,false,true>,
                         cudaFuncAttributeMaxDynamicSharedMemorySize, SMEM_GEMM);
    cudaFuncSetAttribute(k_tf32gemm<false,true,false>,
                         cudaFuncAttributeMaxDynamicSharedMemorySize, SMEM_GEMM);

    dim3 gqkv(RR/128, (BMROWS + 127)/128);   // (3, 86)
    k_tf32gemm<false,false,false><<<gqkv, 256, SMEM_GEMM>>>(p_uniq, p_wqt, bq, nullptr, p_q, BMROWS, RR, RR);
    k_tf32gemm<false,false,false><<<gqkv, 256, SMEM_GEMM>>>(p_uniq, p_wkt, bk, nullptr, p_k, BMROWS, RR, RR);
    k_tf32gemm<false,false,false><<<gqkv, 256, SMEM_GEMM>>>(p_uniq, p_wvt, bv, nullptr, p_v, BMROWS, RR, RR);

    size_t attn_smem = (size_t)(64*64 + 3*64*65) * sizeof(float);
    cudaFuncSetAttribute(k_attn, cudaFuncAttributeMaxDynamicSharedMemorySize, (int)attn_smem);
    k_attn<<<dim3((MMD+63)/64, NHEAD, BB), 256, attn_smem>>>(p_q, p_k, p_v, p_o);

    k_tf32gemm<false,false,false><<<gqkv, 256, SMEM_GEMM>>>(p_o, p_wot, bo, nullptr, p_ao, BMROWS, RR, RR);

    k_resid_ln2<<<NROWS, 128>>>(x, ln2w, ln2b);

    // MLP GEMM1: h1 = tf32round(gelu(xln2 @ w1 + b1))
    k_tf32gemm<true,false,true><<<dim3(HIDD/128, BHWD/128), 256, SMEM_GEMM>>>(
        p_xln2, p_w1t, b1, nullptr, p_h1, BHWD, HIDD, NED);

    // MLP GEMM2: out = h1 @ w2 + b2 + xres
    k_tf32gemm<false,true,false><<<dim3(NED/128, BHWD/128), 256, SMEM_GEMM>>>(
        p_h1, p_w2t, b2, p_xres, (float*)d_out, BHWD, NED, HIDD);
}

// round 8
// speedup vs baseline: 5.0633x; 1.5875x over previous
#include <cuda_runtime.h>
#include <cuda_fp16.h>
#include <math.h>
#include <stdint.h>

// ---------------- problem constants ----------------
#define BB     8
#define HHT    32
#define WWD    32
#define LL     6
#define RR     384
#define NHEAD  6
#define DHD    64
#define NED    2304          // L*R
#define HIDD   9216          // 4*NE
#define MMD    1365          // unique tree nodes
#define BMROWS (BB*MMD)      // 10920
#define BHWD   8192          // B*H*W
#define NROWS  49152         // B*H*W*L

// ---------------- scratch (static device memory; no allocs) ----------------
__device__ float  g_uniq[(size_t)BB*MMD*RR];          // fp32 atomic scatter target
__device__ __half g_uniqh[(size_t)BB*MMD*RR];         // fp16 GEMM operand
__device__ float  g_q[(size_t)BB*MMD*RR];
__device__ float  g_k[(size_t)BB*MMD*RR];
__device__ float  g_v[(size_t)BB*MMD*RR];
__device__ __half g_oattnh[(size_t)BB*MMD*RR];
__device__ float  g_attnout[(size_t)BB*MMD*RR];
__device__ float  g_xres[(size_t)NROWS*RR];
__device__ __half g_xln2h[(size_t)NROWS*RR];
__device__ __half g_h1h[(size_t)BHWD*HIDD];
// fp16 transposed weights (N,K)
__device__ __half g_wqh[RR*RR];
__device__ __half g_wkh[RR*RR];
__device__ __half g_wvh[RR*RR];
__device__ __half g_woh[RR*RR];
__device__ __half g_w1h[(size_t)NED*HIDD];
__device__ __half g_w2h[(size_t)HIDD*NED];

__constant__ int c_offs[LL] = {0, 1024, 1280, 1344, 1360, 1364};

__device__ __forceinline__ float gelu_t(float v) {
    float x3 = v*v*v;
    return 0.5f * v * (1.f + tanhf(0.7978845608028654f * (v + 0.044715f*x3)));
}
__device__ __forceinline__ uint32_t smem_u32(const void* p) {
    uint32_t a;
    asm("{ .reg .u64 t; cvta.to.shared.u64 t, %1; cvt.u32.u64 %0, t; }" : "=r"(a) : "l"(p));
    return a;
}
__device__ __forceinline__ void cp16(uint32_t sa, const void* gp, bool pred) {
    asm volatile("cp.async.ca.shared.global [%0], [%1], 16, %2;"
                 :: "r"(sa), "l"(gp), "r"(pred ? 16u : 0u));
}
__device__ __forceinline__ void cp16u(uint32_t sa, const void* gp) {
    asm volatile("cp.async.ca.shared.global [%0], [%1], 16;" :: "r"(sa), "l"(gp));
}
#define CP_COMMIT() asm volatile("cp.async.commit_group;" ::: "memory")
#define CP_WAIT1()  asm volatile("cp.async.wait_group 1;" ::: "memory")
#define CP_WAIT0()  asm volatile("cp.async.wait_group 0;" ::: "memory")

__device__ __forceinline__ void mma_f16(float& c0, float& c1, float& c2, float& c3,
                                        uint32_t a0, uint32_t a1, uint32_t a2, uint32_t a3,
                                        uint32_t b0, uint32_t b1) {
    asm volatile(
        "mma.sync.aligned.m16n8k16.row.col.f32.f16.f16.f32 "
        "{%0,%1,%2,%3}, {%4,%5,%6,%7}, {%8,%9}, {%0,%1,%2,%3};"
        : "+f"(c0), "+f"(c1), "+f"(c2), "+f"(c3)
        : "r"(a0), "r"(a1), "r"(a2), "r"(a3), "r"(b0), "r"(b1));
}
__device__ __forceinline__ void ldm_x4(uint32_t& r0, uint32_t& r1, uint32_t& r2, uint32_t& r3,
                                       uint32_t addr) {
    asm volatile("ldmatrix.sync.aligned.m8n8.x4.shared.b16 {%0,%1,%2,%3}, [%4];"
                 : "=r"(r0), "=r"(r1), "=r"(r2), "=r"(r3) : "r"(addr));
}
__device__ __forceinline__ void ldm_x2(uint32_t& r0, uint32_t& r1, uint32_t addr) {
    asm volatile("ldmatrix.sync.aligned.m8n8.x2.shared.b16 {%0,%1}, [%2];"
                 : "=r"(r0), "=r"(r1) : "r"(addr));
}

// ---------------- fp32 -> fp16 flat convert (8 elems/thread/iter) ----------------
__global__ void __launch_bounds__(256) k_cvth(const float* __restrict__ in,
                                              __half* __restrict__ out, size_t n8)
{
    size_t i = (size_t)blockIdx.x * blockDim.x + threadIdx.x;
    size_t stride = (size_t)gridDim.x * blockDim.x;
    for (; i < n8; i += stride) {
        float4 v0 = reinterpret_cast<const float4*>(in)[2*i];
        float4 v1 = reinterpret_cast<const float4*>(in)[2*i + 1];
        __half2 h0 = __floats2half2_rn(v0.x, v0.y);
        __half2 h1 = __floats2half2_rn(v0.z, v0.w);
        __half2 h2 = __floats2half2_rn(v1.x, v1.y);
        __half2 h3 = __floats2half2_rn(v1.z, v1.w);
        uint4 o;
        o.x = *reinterpret_cast<uint32_t*>(&h0);
        o.y = *reinterpret_cast<uint32_t*>(&h1);
        o.z = *reinterpret_cast<uint32_t*>(&h2);
        o.w = *reinterpret_cast<uint32_t*>(&h3);
        reinterpret_cast<uint4*>(out)[i] = o;
    }
}

// ---------------- transpose + fp16 convert: in (K,N) fp32 -> out (N,K) fp16 ----------------
__global__ void __launch_bounds__(256) k_cvtT(const float* __restrict__ in,
                                              __half* __restrict__ out, int K, int N)
{
    __shared__ float tile[32][33];
    int n0 = blockIdx.x * 32, k0 = blockIdx.y * 32;
    int tx = threadIdx.x, ty = threadIdx.y;   // 32 x 8
#pragma unroll
    for (int i = 0; i < 4; i++)
        tile[ty + 8*i][tx] = in[(size_t)(k0 + ty + 8*i)*N + n0 + tx];
    __syncthreads();
#pragma unroll
    for (int i = 0; i < 4; i++)
        out[(size_t)(n0 + ty + 8*i)*K + k0 + tx] = __float2half(tile[tx][ty + 8*i]);
}

// =====================================================================
// fp16 tensor-core GEMM: C(Ma,N) = act(A(Ma,K) @ B^T + bias) [+resid]
// A: (Ma,K) fp16 row-major. Bt: (N,K) fp16 row-major (pre-transposed W).
// CTA 128x128, BK=32, 256 thr, warps 2(m) x 4(n), warp 64x32, ldmatrix.
// N % 128 == 0, K % 32 == 0; Ma guarded.
// =====================================================================
#define SROW 80                       // bytes per 32-halves row (64 data + 16 pad)
#define STAGE_A (128*SROW)            // 10240 B
#define STAGE_B (128*SROW)            // 10240 B
#define NSTAGE 3
#define SMEM_GEMM (NSTAGE*(STAGE_A+STAGE_B))   // 61440 B

template<bool DOGELU, bool DORESID, bool OUTHALF>
__global__ void __launch_bounds__(256, 2) k_h16gemm(
    const __half* __restrict__ A, const __half* __restrict__ Bt,
    const float* __restrict__ bias, const float* __restrict__ Rm,
    float* __restrict__ Cf, __half* __restrict__ Ch,
    int Ma, int N, int K)
{
    extern __shared__ __align__(16) char smem[];
    const uint32_t sA = smem_u32(smem);
    const uint32_t sB = sA + NSTAGE*STAGE_A;

    const int tid = threadIdx.x;
    const int wid = tid >> 5, lane = tid & 31;
    const int wm = wid >> 2, wn = wid & 3;   // 2 x 4 warp grid
    const int r = lane >> 2, c4 = lane & 3;

    const int m0 = blockIdx.y * 128, n0 = blockIdx.x * 128;
    const int NC = K >> 5;

    // ldmatrix per-lane offsets
    const int lrA = (lane & 7) + ((lane >> 3) & 1) * 8;   // row within 16
    const int lkA = (lane >> 4) * 16;                      // +8 halves = 16 B
    const int lrB = lane & 7;
    const int lkB = ((lane >> 3) & 1) * 16;

    float acc[4][4][4];
#pragma unroll
    for (int i = 0; i < 4; i++)
#pragma unroll
        for (int j = 0; j < 4; j++)
#pragma unroll
            for (int q = 0; q < 4; q++) acc[i][j][q] = 0.f;

    const int frow = tid >> 2, fchk = (tid & 3);          // fill: row 0..63(x2), 16B chunk
    auto fill = [&](int s, int kc) {
        const int k0 = kc << 5;
#pragma unroll
        for (int p = 0; p < 2; p++) {
            int row = frow + p*64;
            bool ok = (m0 + row) < Ma;
            cp16(sA + (uint32_t)(s*STAGE_A + row*SROW + fchk*16),
                 A + (size_t)(m0 + row)*K + k0 + fchk*8, ok);
        }
#pragma unroll
        for (int p = 0; p < 2; p++) {
            int row = frow + p*64;
            cp16u(sB + (uint32_t)(s*STAGE_B + row*SROW + fchk*16),
                  Bt + (size_t)(n0 + row)*K + k0 + fchk*8);
        }
    };

    fill(0, 0); CP_COMMIT();
    if (NC > 1) { fill(1, 1); CP_COMMIT(); }

    for (int kc = 0; kc < NC; kc++) {
        if (kc + 1 < NC) CP_WAIT1(); else CP_WAIT0();
        __syncthreads();
        const int s = kc % NSTAGE;
        if (kc + 2 < NC) { fill((kc + 2) % NSTAGE, kc + 2); CP_COMMIT(); }

        const uint32_t aBase = sA + s*STAGE_A;
        const uint32_t bBase = sB + s*STAGE_B;
#pragma unroll
        for (int ks = 0; ks < 2; ks++) {
            uint32_t a[4][4], b[4][2];
#pragma unroll
            for (int mf = 0; mf < 4; mf++) {
                uint32_t ad = aBase + (uint32_t)((wm*64 + mf*16 + lrA)*SROW + ks*32 + lkA);
                ldm_x4(a[mf][0], a[mf][1], a[mf][2], a[mf][3], ad);
            }
#pragma unroll
            for (int nf = 0; nf < 4; nf++) {
                uint32_t bd = bBase + (uint32_t)((wn*32 + nf*8 + lrB)*SROW + ks*32 + lkB);
                ldm_x2(b[nf][0], b[nf][1], bd);
            }
#pragma unroll
            for (int mf = 0; mf < 4; mf++)
#pragma unroll
                for (int nf = 0; nf < 4; nf++)
                    mma_f16(acc[mf][nf][0], acc[mf][nf][1], acc[mf][nf][2], acc[mf][nf][3],
                            a[mf][0], a[mf][1], a[mf][2], a[mf][3],
                            b[nf][0], b[nf][1]);
        }
        __syncthreads();
    }

    // ---- epilogue ----
#pragma unroll
    for (int mf = 0; mf < 4; mf++) {
        int grow0 = m0 + wm*64 + mf*16 + r;
#pragma unroll
        for (int nf = 0; nf < 4; nf++) {
            int gcol = n0 + wn*32 + nf*8 + 2*c4;
            float b0 = bias[gcol], b1 = bias[gcol + 1];
#pragma unroll
            for (int hh = 0; hh < 2; hh++) {
                int grow = grow0 + hh*8;
                if (grow < Ma) {
                    float v0 = acc[mf][nf][hh*2 + 0] + b0;
                    float v1 = acc[mf][nf][hh*2 + 1] + b1;
                    if (DOGELU) { v0 = gelu_t(v0); v1 = gelu_t(v1); }
                    if (DORESID) {
                        v0 += Rm[(size_t)grow*N + gcol];
                        v1 += Rm[(size_t)grow*N + gcol + 1];
                    }
                    if (OUTHALF) {
                        __half2 h = __floats2half2_rn(v0, v1);
                        *reinterpret_cast<__half2*>(&Ch[(size_t)grow*N + gcol]) = h;
                    } else {
                        *reinterpret_cast<float2*>(&Cf[(size_t)grow*N + gcol]) = make_float2(v0, v1);
                    }
                }
            }
        }
    }
}

// ---------------- LN1 + segment-mean scatter ----------------
__global__ void __launch_bounds__(128) k_ln1_scatter(
    const float* __restrict__ x, const float* __restrict__ gw, const float* __restrict__ gb)
{
    int row = blockIdx.x;
    int l = row % LL; int t = row / LL;
    int w = t % WWD;  t /= WWD;
    int h = t % HHT;  int b = t / HHT;

    const float* xp = x + (size_t)row * RR;
    int tid = threadIdx.x;
    float v[3]; float s1 = 0.f, s2 = 0.f;
#pragma unroll
    for (int i = 0; i < 3; i++) {
        float vv = xp[tid + i*128];
        v[i] = vv; s1 += vv; s2 += vv*vv;
    }
#pragma unroll
    for (int o = 16; o > 0; o >>= 1) {
        s1 += __shfl_xor_sync(0xffffffffu, s1, o);
        s2 += __shfl_xor_sync(0xffffffffu, s2, o);
    }
    __shared__ float sh[8];
    int wid = tid >> 5, ln = tid & 31;
    if (ln == 0) { sh[wid] = s1; sh[4+wid] = s2; }
    __syncthreads();
    s1 = sh[0]+sh[1]+sh[2]+sh[3];
    s2 = sh[4]+sh[5]+sh[6]+sh[7];
    float mu   = s1 * (1.0f/RR);
    float var  = s2 * (1.0f/RR) - mu*mu;
    float rstd = rsqrtf(var + 1e-5f);

    int id = c_offs[l] + (h >> l) * (WWD >> l) + (w >> l);
    float invc = 1.0f / (float)(1 << (2*l));
    float* up = &g_uniq[((size_t)b*MMD + id)*RR];
#pragma unroll
    for (int i = 0; i < 3; i++) {
        int c = tid + i*128;
        float y = (v[i] - mu) * rstd * gw[c] + gb[c];
        atomicAdd(&up[c], y * invc);
    }
}

// ---------------- residual + LN2 (xln2 emitted fp16) ----------------
__global__ void __launch_bounds__(128) k_resid_ln2(
    const float* __restrict__ x, const float* __restrict__ gw, const float* __restrict__ gb)
{
    int row = blockIdx.x;
    int l = row % LL; int t = row / LL;
    int w = t % WWD;  t /= WWD;
    int h = t % HHT;  int b = t / HHT;
    int id = c_offs[l] + (h >> l) * (WWD >> l) + (w >> l);

    const float* xp = x + (size_t)row*RR;
    const float* ap = &g_attnout[((size_t)b*MMD + id)*RR];
    float* rp = &g_xres[(size_t)row*RR];
    __half* op = &g_xln2h[(size_t)row*RR];

    int tid = threadIdx.x;
    float v[3]; float s1 = 0.f, s2 = 0.f;
#pragma unroll
    for (int i = 0; i < 3; i++) {
        int c = tid + i*128;
        float vv = xp[c] + ap[c];
        rp[c] = vv;
        v[i] = vv; s1 += vv; s2 += vv*vv;
    }
#pragma unroll
    for (int o = 16; o > 0; o >>= 1) {
        s1 += __shfl_xor_sync(0xffffffffu, s1, o);
        s2 += __shfl_xor_sync(0xffffffffu, s2, o);
    }
    __shared__ float sh[8];
    int wid = tid >> 5, ln = tid & 31;
    if (ln == 0) { sh[wid] = s1; sh[4+wid] = s2; }
    __syncthreads();
    s1 = sh[0]+sh[1]+sh[2]+sh[3];
    s2 = sh[4]+sh[5]+sh[6]+sh[7];
    float mu   = s1 * (1.0f/RR);
    float var  = s2 * (1.0f/RR) - mu*mu;
    float rstd = rsqrtf(var + 1e-5f);
#pragma unroll
    for (int i = 0; i < 3; i++) {
        int c = tid + i*128;
        op[c] = __float2half((v[i] - mu) * rstd * gw[c] + gb[c]);
    }
}

// ---------------- flash attention over M tree nodes (fp32 math, fp16 out) ----------------
__global__ void __launch_bounds__(256) k_attn(
    const float* __restrict__ gq, const float* __restrict__ gk,
    const float* __restrict__ gv, __half* __restrict__ go)
{
    extern __shared__ float sm[];
    float* Qs = sm;                   // [64][64]
    float* Ks = sm + 64*64;           // [64][65]
    float* Vs = Ks + 64*65;           // [64][65]
    float* Ps = Vs + 64*65;           // [64][65]

    int rt = blockIdx.x, hh = blockIdx.y, b = blockIdx.z;
    int tid = threadIdx.x;
    int ty = tid >> 4, tx = tid & 15;

    for (int i = tid; i < 64*DHD; i += 256) {
        int r = i >> 6, d = i & 63;
        int m = rt*64 + r;
        Qs[r*64 + d] = (m < MMD) ? gq[((size_t)b*MMD + m)*RR + hh*DHD + d] : 0.f;
    }
    float acc[4][4];
    float mrow[4], lrow[4];
#pragma unroll
    for (int i = 0; i < 4; i++) {
        mrow[i] = -INFINITY; lrow[i] = 0.f;
#pragma unroll
        for (int j = 0; j < 4; j++) acc[i][j] = 0.f;
    }
    __syncthreads();

    int ntiles = (MMD + 63) / 64;
    for (int kt = 0; kt < ntiles; kt++) {
        for (int i = tid; i < 64*DHD; i += 256) {
            int r = i >> 6, d = i & 63;
            int n = kt*64 + r;
            bool ok = (n < MMD);
            size_t base = ((size_t)b*MMD + n)*RR + hh*DHD + d;
            Ks[r*65 + d] = ok ? gk[base] : 0.f;
            Vs[r*65 + d] = ok ? gv[base] : 0.f;
        }
        __syncthreads();

        float s[4][4];
#pragma unroll
        for (int i = 0; i < 4; i++)
#pragma unroll
            for (int j = 0; j < 4; j++) s[i][j] = 0.f;
        for (int d = 0; d < DHD; d++) {
            float av[4], bv[4];
#pragma unroll
            for (int i = 0; i < 4; i++) av[i] = Qs[(ty*4+i)*64 + d];
#pragma unroll
            for (int j = 0; j < 4; j++) bv[j] = Ks[(tx*4+j)*65 + d];
#pragma unroll
            for (int i = 0; i < 4; i++)
#pragma unroll
                for (int j = 0; j < 4; j++) s[i][j] += av[i]*bv[j];
        }
        const float sc = 0.125f;   // 1/sqrt(64)
#pragma unroll
        for (int i = 0; i < 4; i++)
#pragma unroll
            for (int j = 0; j < 4; j++) {
                int n = kt*64 + tx*4 + j;
                s[i][j] = (n < MMD) ? s[i][j]*sc : -INFINITY;
            }

#pragma unroll
        for (int i = 0; i < 4; i++) {
            float mv = fmaxf(fmaxf(s[i][0], s[i][1]), fmaxf(s[i][2], s[i][3]));
#pragma unroll
            for (int o = 8; o > 0; o >>= 1) mv = fmaxf(mv, __shfl_xor_sync(0xffffffffu, mv, o));
            float mn   = fmaxf(mrow[i], mv);
            float corr = __expf(mrow[i] - mn);
            float ps = 0.f;
#pragma unroll
            for (int j = 0; j < 4; j++) {
                float p = __expf(s[i][j] - mn);
                s[i][j] = p; ps += p;
            }
#pragma unroll
            for (int o = 8; o > 0; o >>= 1) ps += __shfl_xor_sync(0xffffffffu, ps, o);
            lrow[i] = lrow[i]*corr + ps;
            mrow[i] = mn;
#pragma unroll
            for (int j = 0; j < 4; j++) {
                acc[i][j] *= corr;
                Ps[(ty*4+i)*65 + tx*4 + j] = s[i][j];
            }
        }
        __syncthreads();

        for (int c = 0; c < 64; c++) {
            float av[4], bv[4];
#pragma unroll
            for (int i = 0; i < 4; i++) av[i] = Ps[(ty*4+i)*65 + c];
#pragma unroll
            for (int j = 0; j < 4; j++) bv[j] = Vs[c*65 + tx*4 + j];
#pragma unroll
            for (int i = 0; i < 4; i++)
#pragma unroll
                for (int j = 0; j < 4; j++) acc[i][j] += av[i]*bv[j];
        }
        __syncthreads();
    }

#pragma unroll
    for (int i = 0; i < 4; i++) {
        int m = rt*64 + ty*4 + i;
        if (m < MMD) {
            float inv_l = 1.0f / lrow[i];
#pragma unroll
            for (int j = 0; j < 4; j++)
                go[((size_t)b*MMD + m)*RR + hh*DHD + tx*4 + j] = __float2half(acc[i][j]*inv_l);
        }
    }
}

// ---------------- launcher ----------------
extern "C" void kernel_launch(void* const* d_in, const int* in_sizes, int n_in,
                              void* d_out, int out_size)
{
    (void)in_sizes; (void)n_in; (void)out_size;
    const float* x    = (const float*)d_in[0];
    const float* ln1w = (const float*)d_in[1];
    const float* ln1b = (const float*)d_in[2];
    const float* ln2w = (const float*)d_in[3];
    const float* ln2b = (const float*)d_in[4];
    const float* wq   = (const float*)d_in[5];
    const float* bq   = (const float*)d_in[6];
    const float* wk   = (const float*)d_in[7];
    const float* bk   = (const float*)d_in[8];
    const float* wv   = (const float*)d_in[9];
    const float* bv   = (const float*)d_in[10];
    const float* wo   = (const float*)d_in[11];
    const float* bo   = (const float*)d_in[12];
    const float* w1   = (const float*)d_in[13];
    const float* b1   = (const float*)d_in[14];
    const float* w2   = (const float*)d_in[15];
    const float* b2   = (const float*)d_in[16];

    float *p_uniq, *p_q, *p_k, *p_v, *p_ao, *p_xres;
    __half *p_uniqh, *p_oh, *p_xln2h, *p_h1h;
    __half *p_wqh, *p_wkh, *p_wvh, *p_woh, *p_w1h, *p_w2h;
    cudaGetSymbolAddress((void**)&p_uniq,  g_uniq);
    cudaGetSymbolAddress((void**)&p_uniqh, g_uniqh);
    cudaGetSymbolAddress((void**)&p_q,     g_q);
    cudaGetSymbolAddress((void**)&p_k,     g_k);
    cudaGetSymbolAddress((void**)&p_v,     g_v);
    cudaGetSymbolAddress((void**)&p_oh,    g_oattnh);
    cudaGetSymbolAddress((void**)&p_ao,    g_attnout);
    cudaGetSymbolAddress((void**)&p_xres,  g_xres);
    cudaGetSymbolAddress((void**)&p_xln2h, g_xln2h);
    cudaGetSymbolAddress((void**)&p_h1h,   g_h1h);
    cudaGetSymbolAddress((void**)&p_wqh,   g_wqh);
    cudaGetSymbolAddress((void**)&p_wkh,   g_wkh);
    cudaGetSymbolAddress((void**)&p_wvh,   g_wvh);
    cudaGetSymbolAddress((void**)&p_woh,   g_woh);
    cudaGetSymbolAddress((void**)&p_w1h,   g_w1h);
    cudaGetSymbolAddress((void**)&p_w2h,   g_w2h);

    cudaMemsetAsync(p_uniq, 0, sizeof(float)*(size_t)BB*MMD*RR, 0);

    // weights -> fp16 transposed (N,K)
    k_cvtT<<<dim3(RR/32, RR/32),     dim3(32,8)>>>(wq, p_wqh, RR, RR);
    k_cvtT<<<dim3(RR/32, RR/32),     dim3(32,8)>>>(wk, p_wkh, RR, RR);
    k_cvtT<<<dim3(RR/32, RR/32),     dim3(32,8)>>>(wv, p_wvh, RR, RR);
    k_cvtT<<<dim3(RR/32, RR/32),     dim3(32,8)>>>(wo, p_woh, RR, RR);
    k_cvtT<<<dim3(HIDD/32, NED/32),  dim3(32,8)>>>(w1, p_w1h, NED, HIDD);
    k_cvtT<<<dim3(NED/32, HIDD/32),  dim3(32,8)>>>(w2, p_w2h, HIDD, NED);

    k_ln1_scatter<<<NROWS, 128>>>(x, ln1w, ln1b);
    k_cvth<<<1024, 256>>>(p_uniq, p_uniqh, (size_t)BB*MMD*RR/8);

    cudaFuncSetAttribute(k_h16gemm<false,false,false>,
                         cudaFuncAttributeMaxDynamicSharedMemorySize, SMEM_GEMM);
    cudaFuncSetAttribute(k_h16gemm<true,false,true>,
                         cudaFuncAttributeMaxDynamicSharedMemorySize, SMEM_GEMM);
    cudaFuncSetAttribute(k_h16gemm<false,true,false>,
                         cudaFuncAttributeMaxDynamicSharedMemorySize, SMEM_GEMM);

    dim3 gqkv(RR/128, (BMROWS + 127)/128);   // (3, 86)
    k_h16gemm<false,false,false><<<gqkv, 256, SMEM_GEMM>>>(
        p_uniqh, p_wqh, bq, nullptr, p_q, nullptr, BMROWS, RR, RR);
    k_h16gemm<false,false,false><<<gqkv, 256, SMEM_GEMM>>>(
        p_uniqh, p_wkh, bk, nullptr, p_k, nullptr, BMROWS, RR, RR);
    k_h16gemm<false,false,false><<<gqkv, 256, SMEM_GEMM>>>(
        p_uniqh, p_wvh, bv, nullptr, p_v, nullptr, BMROWS, RR, RR);

    size_t attn_smem = (size_t)(64*64 + 3*64*65) * sizeof(float);
    cudaFuncSetAttribute(k_attn, cudaFuncAttributeMaxDynamicSharedMemorySize, (int)attn_smem);
    k_attn<<<dim3((MMD+63)/64, NHEAD, BB), 256, attn_smem>>>(p_q, p_k, p_v, p_oh);

    k_h16gemm<false,false,false><<<gqkv, 256, SMEM_GEMM>>>(
        p_oh, p_woh, bo, nullptr, p_ao, nullptr, BMROWS, RR, RR);

    k_resid_ln2<<<NROWS, 128>>>(x, ln2w, ln2b);

    // MLP GEMM1: h1 = fp16(gelu(xln2 @ w1 + b1))
    k_h16gemm<true,false,true><<<dim3(HIDD/128, BHWD/128), 256, SMEM_GEMM>>>(
        p_xln2h, p_w1h, b1, nullptr, nullptr, p_h1h, BHWD, HIDD, NED);

    // MLP GEMM2: out = h1 @ w2 + b2 + xres
    k_h16gemm<false,true,false><<<dim3(NED/128, BHWD/128), 256, SMEM_GEMM>>>(
        p_h1h, p_w2h, b2, p_xres, (float*)d_out, nullptr, BHWD, NED, HIDD);
}